// round 15
// baseline (speedup 1.0000x reference)
#include <cuda_runtime.h>
#include <cuda_fp16.h>
#include <math.h>
#include <stdint.h>

// Problem constants
#define BQ 2
#define CQ 128
#define TQ 32
#define NQ 512
#define PQ (TQ * NQ)      // 16384 points per batch
#define KQ 16
#define HIDQ 512
#define OUTC 132
#define THREEN 1536

// ---------------------------------------------------------------------------
// Device scratch (static — no allocations allowed)
// ---------------------------------------------------------------------------
__device__ float    g_xpm[BQ * PQ * CQ];   // x transposed (b,p,c), full precision (residual)
__device__ uint32_t g_xh[BQ * PQ * 64];    // x transposed, half2 packed (QKV input)
__device__ float    g_q[BQ * PQ * CQ];     // q projection, fp32, point-major
__device__ uint32_t g_kvh[BQ * PQ * 128];  // per point: [0..63] kx half2, [64..127] vx half2
__device__ int      g_idx[BQ * PQ * KQ];   // neighbor composite index t_eff*N + n'
__device__ uint32_t g_hh[BQ * PQ * 64];    // post-attn+BN h, half2 packed (W1 input)
__device__ uint32_t g_hidh[BQ * PQ * (HIDQ / 2)];  // leaky(W1@h), half2 packed (W2 input)
__device__ uint32_t g_wqh[(CQ * CQ) / 2];  // Wq half2 packed along k
__device__ uint32_t g_wkh[(CQ * CQ) / 2];  // Wk
__device__ uint32_t g_wvh[(CQ * CQ) / 2];  // Wv
__device__ uint32_t g_w1h[(HIDQ * CQ) / 2];
__device__ uint32_t g_w2h[(CQ * HIDQ) / 2];

// ---------------------------------------------------------------------------
// fp16 / async helpers
// ---------------------------------------------------------------------------
__device__ __forceinline__ void mma_f16(float c[4],
                                        uint32_t a0, uint32_t a1, uint32_t a2, uint32_t a3,
                                        uint32_t b0, uint32_t b1)
{
    asm volatile(
        "mma.sync.aligned.m16n8k16.row.col.f32.f16.f16.f32 "
        "{%0,%1,%2,%3},{%4,%5,%6,%7},{%8,%9},{%0,%1,%2,%3};"
        : "+f"(c[0]), "+f"(c[1]), "+f"(c[2]), "+f"(c[3])
        : "r"(a0), "r"(a1), "r"(a2), "r"(a3), "r"(b0), "r"(b1));
}

__device__ __forceinline__ void cp16(uint32_t* dst_smem, const void* src)
{
    uint32_t d = (uint32_t)__cvta_generic_to_shared(dst_smem);
    asm volatile("cp.async.cg.shared.global [%0], [%1], 16;" :: "r"(d), "l"(src));
}
__device__ __forceinline__ void cp_commit() { asm volatile("cp.async.commit_group;" ::: "memory"); }
template<int N>
__device__ __forceinline__ void cp_wait() { asm volatile("cp.async.wait_group %0;" :: "n"(N) : "memory"); }

// ---------------------------------------------------------------------------
// K_pre: pack all weights to half2.
// ---------------------------------------------------------------------------
__global__ void k_roundw(const float* __restrict__ Wq, const float* __restrict__ Wk,
                         const float* __restrict__ Wv, const float* __restrict__ W1,
                         const float* __restrict__ W2)
{
    int i = blockIdx.x * 256 + threadIdx.x;   // 0 .. 65535
    if (i < (CQ * CQ) / 2) {
        __half2 hq = __floats2half2_rn(Wq[2 * i], Wq[2 * i + 1]);
        __half2 hk = __floats2half2_rn(Wk[2 * i], Wk[2 * i + 1]);
        __half2 hv = __floats2half2_rn(Wv[2 * i], Wv[2 * i + 1]);
        g_wqh[i] = *(uint32_t*)&hq;
        g_wkh[i] = *(uint32_t*)&hk;
        g_wvh[i] = *(uint32_t*)&hv;
    }
    if (i < (HIDQ * CQ) / 2) {
        __half2 h1 = __floats2half2_rn(W1[2 * i], W1[2 * i + 1]);
        g_w1h[i] = *(uint32_t*)&h1;
        __half2 h2 = __floats2half2_rn(W2[2 * i], W2[2 * i + 1]);
        g_w2h[i] = *(uint32_t*)&h2;
    }
}

// ---------------------------------------------------------------------------
// K0: transpose x (B,C,P) -> g_xpm (fp32) and g_xh (half2 packed), (B,P,C).
// Also writes out channels 0..3 directly.
// ---------------------------------------------------------------------------
__global__ void k_transpose(const float* __restrict__ x, float* __restrict__ out)
{
    __shared__ float tile[32][33];
    int b = blockIdx.z;
    int p0 = blockIdx.x * 32;
    int c0 = blockIdx.y * 32;
    const float* xb = x + (size_t)b * CQ * PQ;
    int tx = threadIdx.x, ty = threadIdx.y;
#pragma unroll
    for (int i = 0; i < 32; i += 8) {
        float v = xb[(size_t)(c0 + ty + i) * PQ + p0 + tx];
        tile[ty + i][tx] = v;
        if (c0 == 0 && (ty + i) < 4)
            out[(size_t)b * OUTC * PQ + (size_t)(ty + i) * PQ + p0 + tx] = v;
    }
    __syncthreads();
    float* op = g_xpm + (size_t)b * PQ * CQ;
#pragma unroll
    for (int i = 0; i < 32; i += 8) {
        int p = p0 + ty + i;
        op[(size_t)p * CQ + c0 + tx] = tile[tx][ty + i];
        if (tx < 16) {
            __half2 h = __floats2half2_rn(tile[2 * tx][ty + i], tile[2 * tx + 1][ty + i]);
            g_xh[(size_t)(b * PQ + p) * 64 + c0 / 2 + tx] = *(uint32_t*)&h;
        }
    }
}

// ---------------------------------------------------------------------------
// K1: top-K neighbor selection (exact semantics). Candidate-batched: each
// warp scans the 48x32 candidates ONCE per group of 4 points, amortizing the
// LDS loads and running 4 independent insertion chains (ILP). Merge uses
// exact u64 keys; exhaustion check hoisted out of the merge loop
// (conservative: may trigger the exact fallback slightly more often).
// ---------------------------------------------------------------------------
__global__ void __launch_bounds__(256) k_topk(const float* __restrict__ x)
{
    int t = blockIdx.x, b = blockIdx.y, z = blockIdx.z;
    __shared__ float sc[3][THREEN];
    const float* xb = x + (size_t)b * CQ * PQ;
    int tid = threadIdx.x;

    for (int i = tid; i < 3 * THREEN; i += 256) {
        int c = i / THREEN, m = i % THREEN;
        int j = m >> 9, nn = m & 511;
        int te = t - 1 + j;
        te = te < 0 ? 0 : (te > TQ - 1 ? TQ - 1 : te);
        sc[c][m] = xb[(size_t)c * PQ + te * NQ + nn];
    }
    __syncthreads();

    const unsigned FULL = 0xffffffffu;
    const float FINF = __int_as_float(0x7f800000);
    int lane = tid & 31, w = tid >> 5;

#pragma unroll 1
    for (int grp = 0; grp < 2; grp++) {
        const int n0 = z * 64 + w * 8 + grp * 4;

        float ax[4], ay[4], az[4];
#pragma unroll
        for (int pp = 0; pp < 4; pp++) {
            ax[pp] = sc[0][512 + n0 + pp];
            ay[pp] = sc[1][512 + n0 + pp];
            az[pp] = sc[2][512 + n0 + pp];
        }

        float e[4][4];
        int   q[4][4];
#pragma unroll
        for (int pp = 0; pp < 4; pp++) {
            e[pp][0] = FINF; e[pp][1] = FINF; e[pp][2] = FINF; e[pp][3] = FINF;
            q[pp][0] = 0;    q[pp][1] = 0;    q[pp][2] = 0;    q[pp][3] = 0;
        }

        // candidate-batched scan: load coords once, update 4 points
#pragma unroll 4
        for (int jj = 0; jj < 48; jj++) {
            int m = jj * 32 + lane;
            float bx = sc[0][m], by = sc[1][m], bz = sc[2][m];
#pragma unroll
            for (int pp = 0; pp < 4; pp++) {
                float dx = bx - ax[pp];
                float dy = by - ay[pp];
                float dz = bz - az[pp];
                float dc = dx * dx + dy * dy + dz * dz;
                bool l0 = dc < e[pp][0], l1 = dc < e[pp][1];
                bool l2 = dc < e[pp][2], l3 = dc < e[pp][3];
                e[pp][3] = l3 ? (l2 ? e[pp][2] : dc) : e[pp][3];
                q[pp][3] = l3 ? (l2 ? q[pp][2] : m) : q[pp][3];
                e[pp][2] = l2 ? (l1 ? e[pp][1] : dc) : e[pp][2];
                q[pp][2] = l2 ? (l1 ? q[pp][1] : m) : q[pp][2];
                e[pp][1] = l1 ? (l0 ? e[pp][0] : dc) : e[pp][1];
                q[pp][1] = l1 ? (l0 ? q[pp][0] : m) : q[pp][1];
                e[pp][0] = l0 ? dc : e[pp][0];
                q[pp][0] = l0 ? m : q[pp][0];
            }
        }

        // per-point merge + (rare) exact fallback
#pragma unroll 1
        for (int pp = 0; pp < 4; pp++) {
            const int n = n0 + pp;
            float s0 = e[pp][0], s1 = e[pp][1], s2 = e[pp][2], s3 = e[pp][3];
            int   m0 = q[pp][0], m1 = q[pp][1], m2 = q[pp][2], m3 = q[pp][3];

            int ptr = 0;
            int* orow = g_idx + ((size_t)(b * TQ + t) * NQ + n) * KQ;
#pragma unroll
            for (int it = 0; it < KQ; it++) {
                unsigned long long mykey =
                    ((unsigned long long)__float_as_uint(s0) << 32) | (unsigned)m0;
                unsigned long long k = mykey;
#pragma unroll
                for (int off = 16; off; off >>= 1) {
                    unsigned long long o = __shfl_xor_sync(FULL, k, off);
                    if (o < k) k = o;
                }
                if (mykey == k) {
                    s0 = s1; m0 = m1; s1 = s2; m1 = m2; s2 = s3; m2 = m3;
                    s3 = FINF; m3 = 0; ptr++;
                }
                if (lane == 0) {
                    int m = (int)(k & 0xffffffffu);
                    int jwin = m >> 9, nwin = m & 511;
                    int te = t - 1 + jwin;
                    te = te < 0 ? 0 : (te > TQ - 1 ? TQ - 1 : te);
                    orow[it] = te * NQ + nwin;
                }
            }

            // conservative exhaustion check (a lane that emptied its 4 slots
            // might have owned the next pick) -> exact fallback
            if (__any_sync(FULL, ptr >= 4)) {
                unsigned long long removed = 0ull;
                for (int it = 0; it < KQ; it++) {
                    float best = 3.4e38f;
                    int bj = 0;
#pragma unroll
                    for (int jj = 0; jj < 48; jj++) {
                        int m = jj * 32 + lane;
                        float dx = sc[0][m] - ax[pp];
                        float dy = sc[1][m] - ay[pp];
                        float dz = sc[2][m] - az[pp];
                        float dc = dx * dx + dy * dy + dz * dz;
                        bool alive = !(removed & (1ull << jj));
                        if (alive && dc < best) { best = dc; bj = jj; }
                    }
                    int bm = bj * 32 + lane;
#pragma unroll
                    for (int off = 16; off; off >>= 1) {
                        float od = __shfl_xor_sync(FULL, best, off);
                        int   om = __shfl_xor_sync(FULL, bm, off);
                        if (od < best || (od == best && om < bm)) { best = od; bm = om; }
                    }
                    if ((bm & 31) == lane) removed |= (1ull << (bm >> 5));
                    if (lane == 0) {
                        int jwin = bm >> 9, nwin = bm & 511;
                        int te = t - 1 + jwin;
                        te = te < 0 ? 0 : (te > TQ - 1 ? TQ - 1 : te);
                        orow[it] = te * NQ + nwin;
                    }
                }
            }
        }
    }
}

// ---------------------------------------------------------------------------
// Shared fp16 A-resident GEMM pass (unchanged from round 14).
// ---------------------------------------------------------------------------
__device__ __forceinline__ void gemm_f16_Ares_pass(const uint32_t* __restrict__ Ah,
                                                   uint32_t* __restrict__ Bs,
                                                   const uint32_t* __restrict__ Wg,
                                                   float acc[4][4][4], int tid)
{
    const int lane = tid & 31, wid = tid >> 5;
    const int gid = lane >> 2, tig = lane & 3;
    const int mbase = (wid & 1) * 64, nbase = (wid >> 1) * 32;
    const int r0 = tid >> 2, s0 = (tid & 3) * 4;
    const int r1 = r0 + 64;

    cp16(&Bs[r0 * 20 + s0], Wg + (size_t)r0 * 64 + s0);
    cp16(&Bs[r1 * 20 + s0], Wg + (size_t)r1 * 64 + s0);
    cp_commit();

#pragma unroll 1
    for (int kc = 0; kc < 4; kc++) {
        const int st = kc & 1;
        cp_wait<0>();
        __syncthreads();
        if (kc + 1 < 4) {
            const int k0g = (kc + 1) * 16;
            uint32_t* Bd = Bs + (st ^ 1) * (128 * 20);
            cp16(&Bd[r0 * 20 + s0], Wg + (size_t)r0 * 64 + k0g + s0);
            cp16(&Bd[r1 * 20 + s0], Wg + (size_t)r1 * 64 + k0g + s0);
            cp_commit();
        }
        const uint32_t* Bc = Bs + st * (128 * 20);

#pragma unroll
        for (int ks = 0; ks < 2; ks++) {
            const int ka = kc * 16 + ks * 8;
            const int kb = ks * 8;
            uint32_t af[4][4], bf[4][2];
#pragma unroll
            for (int mt = 0; mt < 4; mt++) {
                int m = mbase + mt * 16 + gid;
                af[mt][0] = Ah[m * 68 + ka + tig];
                af[mt][1] = Ah[(m + 8) * 68 + ka + tig];
                af[mt][2] = Ah[m * 68 + ka + 4 + tig];
                af[mt][3] = Ah[(m + 8) * 68 + ka + 4 + tig];
            }
#pragma unroll
            for (int nt = 0; nt < 4; nt++) {
                int n = nbase + nt * 8 + gid;
                bf[nt][0] = Bc[n * 20 + kb + tig];
                bf[nt][1] = Bc[n * 20 + kb + 4 + tig];
            }
#pragma unroll
            for (int mt = 0; mt < 4; mt++)
#pragma unroll
                for (int nt = 0; nt < 4; nt++)
                    mma_f16(acc[mt][nt], af[mt][0], af[mt][1], af[mt][2], af[mt][3],
                            bf[nt][0], bf[nt][1]);
        }
    }
}

#define F16_ARES_SMEM ((128 * 68 + 2 * 128 * 20) * 4)   // 55296 B

// K2: merged QKV projection, full fp16 (unchanged from round 14).
__global__ void __launch_bounds__(256) k_gemm_qkv()
{
    extern __shared__ uint32_t sm[];
    uint32_t* Ah = sm;                    // [128][68]
    uint32_t* Bs = sm + 128 * 68;         // [2][128][20]

    const int b = blockIdx.y;
    const int p0 = blockIdx.x * 128;
    const int tid = threadIdx.x;
    const uint32_t* A = g_xh + (size_t)(b * PQ + p0) * 64;

#pragma unroll
    for (int it = 0; it < 8; it++) {
        int id = tid + it * 256;
        int r = id >> 4, seg = (id & 15) * 4;
        cp16(&Ah[r * 68 + seg], A + (size_t)r * 64 + seg);
    }
    cp_commit();

    const int lane = tid & 31, wid = tid >> 5;
    const int gid = lane >> 2, tig = lane & 3;

#pragma unroll 1
    for (int cq = 0; cq < 3; cq++) {
        const uint32_t* Wg = (cq == 0) ? g_wqh : ((cq == 1) ? g_wkh : g_wvh);
        float acc[4][4][4] = {};
        gemm_f16_Ares_pass(Ah, Bs, Wg, acc, tid);

        const int prow = b * PQ + p0 + (wid & 1) * 64;
        if (cq == 0) {
            float* base = g_q + (size_t)prow * CQ + (wid >> 1) * 32;
#pragma unroll
            for (int mt = 0; mt < 4; mt++) {
                int r = mt * 16 + gid;
#pragma unroll
                for (int nt = 0; nt < 4; nt++) {
                    int c = nt * 8 + tig * 2;
                    *(float2*)(base + (size_t)r * CQ + c)       = make_float2(acc[mt][nt][0], acc[mt][nt][1]);
                    *(float2*)(base + (size_t)(r + 8) * CQ + c) = make_float2(acc[mt][nt][2], acc[mt][nt][3]);
                }
            }
        } else {
            uint32_t* base = g_kvh + (size_t)prow * 128 + (cq - 1) * 64 + (wid >> 1) * 16;
#pragma unroll
            for (int mt = 0; mt < 4; mt++) {
                int r = mt * 16 + gid;
#pragma unroll
                for (int nt = 0; nt < 4; nt++) {
                    int h2i = nt * 4 + tig;
                    __half2 lo = __floats2half2_rn(acc[mt][nt][0], acc[mt][nt][1]);
                    __half2 hi = __floats2half2_rn(acc[mt][nt][2], acc[mt][nt][3]);
                    base[(size_t)r * 128 + h2i]       = *(uint32_t*)&lo;
                    base[(size_t)(r + 8) * 128 + h2i] = *(uint32_t*)&hi;
                }
            }
        }
    }
}

// ---------------------------------------------------------------------------
// K3: attention + residual + BN (unchanged from round 14).
// ---------------------------------------------------------------------------
__global__ void __launch_bounds__(256) k_attn(const float* __restrict__ gamma,
                                              const float* __restrict__ beta,
                                              const float* __restrict__ mean,
                                              const float* __restrict__ var)
{
    __shared__ float s_scale[CQ], s_shift[CQ];
    int tid = threadIdx.x;
    if (tid < CQ) {
        float sc = gamma[tid] * rsqrtf(var[tid] + 1e-5f);
        s_scale[tid] = sc;
        s_shift[tid] = beta[tid] - mean[tid] * sc;
    }
    __syncthreads();

    int lane = tid & 31, w = tid >> 5;
    const float rs = 0.17677669529663687f; // 1/sqrt(32)

    for (int i = 0; i < 8; i++) {
        int g = blockIdx.x * 64 + w * 8 + i;
        int b = g >> 14;
        int bbase = b << 14;

        float4 qv = ((const float4*)(g_q + (size_t)g * CQ))[lane];

        const uint32_t* kvrow = g_kvh + (size_t)g * 128;
        uint2 su = *(const uint2*)(kvrow + 2 * lane);
        uint2 vu = *(const uint2*)(kvrow + 64 + 2 * lane);
        float2 k0 = __half22float2(*(__half2*)&su.x);
        float2 k1 = __half22float2(*(__half2*)&su.y);
        float2 v0 = __half22float2(*(__half2*)&vu.x);
        float2 v1 = __half22float2(*(__half2*)&vu.y);

        const int* irow = g_idx + (size_t)g * KQ;
        int myidx = irow[lane & 15];

        float dself;
        {
            float p = qv.x * k0.x + qv.y * k0.y + qv.z * k1.x + qv.w * k1.y;
            p += __shfl_xor_sync(0xffffffffu, p, 1);
            p += __shfl_xor_sync(0xffffffffu, p, 2);
            p += __shfl_xor_sync(0xffffffffu, p, 4);
            dself = p;
        }

        float e[16];
#pragma unroll
        for (int k = 0; k < 16; k++) {
            int nb = __shfl_sync(0xffffffffu, myidx, k);
            uint2 ku = *(const uint2*)(g_kvh + (size_t)(bbase + nb) * 128 + 2 * lane);
            float2 f0 = __half22float2(*(__half2*)&ku.x);
            float2 f1 = __half22float2(*(__half2*)&ku.y);
            float p = qv.x * f0.x + qv.y * f0.y + qv.z * f1.x + qv.w * f1.y;
            p += __shfl_xor_sync(0xffffffffu, p, 1);
            p += __shfl_xor_sync(0xffffffffu, p, 2);
            p += __shfl_xor_sync(0xffffffffu, p, 4);
            e[k] = (dself - p) * rs;
        }

        float mx = e[0];
#pragma unroll
        for (int k = 1; k < 16; k++) mx = fmaxf(mx, e[k]);
        float s = 0.f;
#pragma unroll
        for (int k = 0; k < 16; k++) { e[k] = __expf(e[k] - mx); s += e[k]; }
        float inv = 1.0f / s;

        float4 acc = make_float4(v0.x, v0.y, v1.x, v1.y);
#pragma unroll
        for (int k = 0; k < 16; k++) {
            int nb = __shfl_sync(0xffffffffu, myidx, k);
            uint2 wu = *(const uint2*)(g_kvh + (size_t)(bbase + nb) * 128 + 64 + 2 * lane);
            float2 f0 = __half22float2(*(__half2*)&wu.x);
            float2 f1 = __half22float2(*(__half2*)&wu.y);
            float a = e[k] * inv;
            acc.x -= a * f0.x; acc.y -= a * f0.y;
            acc.z -= a * f1.x; acc.w -= a * f1.y;
        }

        const float4* xp = (const float4*)(g_xpm + (size_t)g * CQ);
        float4 xv = xp[lane];
        int c = lane * 4;
        float h0 = (xv.x + acc.x) * s_scale[c + 0] + s_shift[c + 0];
        float h1 = (xv.y + acc.y) * s_scale[c + 1] + s_shift[c + 1];
        float h2 = (xv.z + acc.z) * s_scale[c + 2] + s_shift[c + 2];
        float h3 = (xv.w + acc.w) * s_scale[c + 3] + s_shift[c + 3];
        __half2 lo = __floats2half2_rn(h0, h1);
        __half2 hi = __floats2half2_rn(h2, h3);
        ((uint2*)(g_hh + (size_t)g * 64))[lane] = make_uint2(*(uint32_t*)&lo, *(uint32_t*)&hi);
    }
}

// ---------------------------------------------------------------------------
// K4: hid = leaky(W1 @ h), fp16 (unchanged from round 14). grid (PQ/128, B).
// ---------------------------------------------------------------------------
__global__ void __launch_bounds__(256) k_gemm_w1()
{
    extern __shared__ uint32_t sm[];
    uint32_t* Ah = sm;                    // [128][68]
    uint32_t* Bs = sm + 128 * 68;         // [2][128][20]

    const int b = blockIdx.y;
    const int p0 = blockIdx.x * 128;
    const int tid = threadIdx.x;
    const uint32_t* A = g_hh + (size_t)(b * PQ + p0) * 64;

#pragma unroll
    for (int it = 0; it < 8; it++) {
        int id = tid + it * 256;
        int r = id >> 4, seg = (id & 15) * 4;
        cp16(&Ah[r * 68 + seg], A + (size_t)r * 64 + seg);
    }
    cp_commit();

    const int lane = tid & 31, wid = tid >> 5;
    const int gid = lane >> 2, tig = lane & 3;

#pragma unroll 1
    for (int nt4 = 0; nt4 < 4; nt4++) {
        const int co0 = nt4 * 128;
        float acc[4][4][4] = {};
        gemm_f16_Ares_pass(Ah, Bs, g_w1h + (size_t)co0 * 64, acc, tid);

        uint32_t* base = g_hidh + (size_t)(b * PQ + p0 + (wid & 1) * 64) * (HIDQ / 2)
                       + co0 / 2 + (wid >> 1) * 16;
#pragma unroll
        for (int mt = 0; mt < 4; mt++) {
            int r = mt * 16 + gid;
#pragma unroll
            for (int nt = 0; nt < 4; nt++) {
                int h2i = nt * 4 + tig;
                float v0 = acc[mt][nt][0], v1 = acc[mt][nt][1];
                float v2 = acc[mt][nt][2], v3 = acc[mt][nt][3];
                v0 = v0 > 0.f ? v0 : 0.2f * v0;
                v1 = v1 > 0.f ? v1 : 0.2f * v1;
                v2 = v2 > 0.f ? v2 : 0.2f * v2;
                v3 = v3 > 0.f ? v3 : 0.2f * v3;
                __half2 lo = __floats2half2_rn(v0, v1);
                __half2 hi = __floats2half2_rn(v2, v3);
                base[(size_t)r * (HIDQ / 2) + h2i]       = *(uint32_t*)&lo;
                base[(size_t)(r + 8) * (HIDQ / 2) + h2i] = *(uint32_t*)&hi;
            }
        }
    }
}

// ---------------------------------------------------------------------------
// K5: y = W2 @ hid, fp16 streaming (unchanged from round 14).
// ---------------------------------------------------------------------------
__global__ void __launch_bounds__(256) k_gemm_w2(float* __restrict__ out)
{
    __shared__ uint32_t As[2][128 * 20];
    __shared__ uint32_t Bs[2][128 * 20];

    const int b = blockIdx.z;
    const int p0 = blockIdx.x * 128;
    const int tid = threadIdx.x;
    const uint32_t* Ag = g_hidh + (size_t)(b * PQ + p0) * (HIDQ / 2);

    const int lane = tid & 31, wid = tid >> 5;
    const int gid = lane >> 2, tig = lane & 3;
    const int mbase = (wid & 1) * 64, nbase = (wid >> 1) * 32;
    const int r0 = tid >> 2, s0 = (tid & 3) * 4;
    const int r1 = r0 + 64;

    float acc[4][4][4] = {};

    cp16(&As[0][r0 * 20 + s0], Ag + (size_t)r0 * (HIDQ / 2) + s0);
    cp16(&As[0][r1 * 20 + s0], Ag + (size_t)r1 * (HIDQ / 2) + s0);
    cp16(&Bs[0][r0 * 20 + s0], g_w2h + (size_t)r0 * (HIDQ / 2) + s0);
    cp16(&Bs[0][r1 * 20 + s0], g_w2h + (size_t)r1 * (HIDQ / 2) + s0);
    cp_commit();

#pragma unroll 1
    for (int kc = 0; kc < 16; kc++) {
        const int st = kc & 1;
        cp_wait<0>();
        __syncthreads();
        if (kc + 1 < 16) {
            const int k0g = (kc + 1) * 16;
            cp16(&As[st ^ 1][r0 * 20 + s0], Ag + (size_t)r0 * (HIDQ / 2) + k0g + s0);
            cp16(&As[st ^ 1][r1 * 20 + s0], Ag + (size_t)r1 * (HIDQ / 2) + k0g + s0);
            cp16(&Bs[st ^ 1][r0 * 20 + s0], g_w2h + (size_t)r0 * (HIDQ / 2) + k0g + s0);
            cp16(&Bs[st ^ 1][r1 * 20 + s0], g_w2h + (size_t)r1 * (HIDQ / 2) + k0g + s0);
            cp_commit();
        }

#pragma unroll
        for (int ks = 0; ks < 2; ks++) {
            const int k0 = ks * 8;
            uint32_t af[4][4], bf[4][2];
#pragma unroll
            for (int mt = 0; mt < 4; mt++) {
                int m = mbase + mt * 16 + gid;
                af[mt][0] = As[st][m * 20 + k0 + tig];
                af[mt][1] = As[st][(m + 8) * 20 + k0 + tig];
                af[mt][2] = As[st][m * 20 + k0 + 4 + tig];
                af[mt][3] = As[st][(m + 8) * 20 + k0 + 4 + tig];
            }
#pragma unroll
            for (int nt = 0; nt < 4; nt++) {
                int n = nbase + nt * 8 + gid;
                bf[nt][0] = Bs[st][n * 20 + k0 + tig];
                bf[nt][1] = Bs[st][n * 20 + k0 + 4 + tig];
            }
#pragma unroll
            for (int mt = 0; mt < 4; mt++)
#pragma unroll
                for (int nt = 0; nt < 4; nt++)
                    mma_f16(acc[mt][nt], af[mt][0], af[mt][1], af[mt][2], af[mt][3],
                            bf[nt][0], bf[nt][1]);
        }
    }

    float* ob = out + (size_t)b * OUTC * PQ + (size_t)4 * PQ;
    int rbase = p0 + mbase;
#pragma unroll
    for (int mt = 0; mt < 4; mt++) {
        int r = rbase + mt * 16 + gid;
#pragma unroll
        for (int nt = 0; nt < 4; nt++) {
            int c = nbase + nt * 8 + tig * 2;
            ob[(size_t)c * PQ + r]           = acc[mt][nt][0];
            ob[(size_t)(c + 1) * PQ + r]     = acc[mt][nt][1];
            ob[(size_t)c * PQ + r + 8]       = acc[mt][nt][2];
            ob[(size_t)(c + 1) * PQ + r + 8] = acc[mt][nt][3];
        }
    }
}

// ---------------------------------------------------------------------------
extern "C" void kernel_launch(void* const* d_in, const int* in_sizes, int n_in,
                              void* d_out, int out_size)
{
    const float* x     = (const float*)d_in[0];
    const float* Wq    = (const float*)d_in[1];
    const float* Wk    = (const float*)d_in[2];
    const float* Wv    = (const float*)d_in[3];
    const float* W1    = (const float*)d_in[4];
    const float* W2    = (const float*)d_in[5];
    const float* gamma = (const float*)d_in[6];
    const float* beta  = (const float*)d_in[7];
    const float* mean  = (const float*)d_in[8];
    const float* var   = (const float*)d_in[9];
    float* out = (float*)d_out;

    static cudaStream_t s2;
    static cudaEvent_t evFork, evJoin;
    static int init_done = 0;
    if (!init_done) {
        cudaFuncSetAttribute(k_gemm_qkv, cudaFuncAttributeMaxDynamicSharedMemorySize, F16_ARES_SMEM);
        cudaFuncSetAttribute(k_gemm_w1,  cudaFuncAttributeMaxDynamicSharedMemorySize, F16_ARES_SMEM);
        cudaStreamCreateWithFlags(&s2, cudaStreamNonBlocking);
        cudaEventCreateWithFlags(&evFork, cudaEventDisableTiming);
        cudaEventCreateWithFlags(&evJoin, cudaEventDisableTiming);
        init_done = 1;
    }

    // Round-8 structure: single fork for topk, everything else serial full-grid.
    cudaEventRecord(evFork, 0);
    cudaStreamWaitEvent(s2, evFork, 0);
    k_topk<<<dim3(TQ, BQ, 8), 256, 0, s2>>>(x);
    cudaEventRecord(evJoin, s2);

    k_roundw<<<256, 256>>>(Wq, Wk, Wv, W1, W2);
    k_transpose<<<dim3(PQ / 32, CQ / 32, BQ), dim3(32, 8)>>>(x, out);
    k_gemm_qkv<<<dim3(PQ / 128, BQ), 256, F16_ARES_SMEM>>>();

    cudaStreamWaitEvent(0, evJoin, 0);
    k_attn<<<dim3((BQ * PQ) / 64, 1, 1), 256>>>(gamma, beta, mean, var);
    k_gemm_w1<<<dim3(PQ / 128, BQ), 256, F16_ARES_SMEM>>>();
    k_gemm_w2<<<dim3(PQ / 128, 1, BQ), 256>>>(out);
}

// round 16
// speedup vs baseline: 1.4820x; 1.4820x over previous
#include <cuda_runtime.h>
#include <cuda_fp16.h>
#include <math.h>
#include <stdint.h>

// Problem constants
#define BQ 2
#define CQ 128
#define TQ 32
#define NQ 512
#define PQ (TQ * NQ)      // 16384 points per batch
#define KQ 16
#define HIDQ 512
#define OUTC 132
#define THREEN 1536

// ---------------------------------------------------------------------------
// Device scratch (static — no allocations allowed)
// ---------------------------------------------------------------------------
__device__ float    g_xpm[BQ * PQ * CQ];   // x transposed (b,p,c), full precision (residual)
__device__ uint32_t g_xh[BQ * PQ * 64];    // x transposed, half2 packed (QKV input)
__device__ float    g_q[BQ * PQ * CQ];     // q projection, fp32, point-major
__device__ uint32_t g_kvh[BQ * PQ * 128];  // per point: [0..63] kx half2, [64..127] vx half2
__device__ int      g_idx[BQ * PQ * KQ];   // neighbor composite index t_eff*N + n'
__device__ uint32_t g_hh[BQ * PQ * 64];    // post-attn+BN h, half2 packed (W1 input)
__device__ uint32_t g_hidh[BQ * PQ * (HIDQ / 2)];  // leaky(W1@h), half2 packed (W2 input)
__device__ uint32_t g_wqh[(CQ * CQ) / 2];  // Wq half2 packed along k
__device__ uint32_t g_wkh[(CQ * CQ) / 2];  // Wk
__device__ uint32_t g_wvh[(CQ * CQ) / 2];  // Wv
__device__ uint32_t g_w1h[(HIDQ * CQ) / 2];
__device__ uint32_t g_w2h[(CQ * HIDQ) / 2];

// ---------------------------------------------------------------------------
// fp16 / async helpers
// ---------------------------------------------------------------------------
__device__ __forceinline__ void mma_f16(float c[4],
                                        uint32_t a0, uint32_t a1, uint32_t a2, uint32_t a3,
                                        uint32_t b0, uint32_t b1)
{
    asm volatile(
        "mma.sync.aligned.m16n8k16.row.col.f32.f16.f16.f32 "
        "{%0,%1,%2,%3},{%4,%5,%6,%7},{%8,%9},{%0,%1,%2,%3};"
        : "+f"(c[0]), "+f"(c[1]), "+f"(c[2]), "+f"(c[3])
        : "r"(a0), "r"(a1), "r"(a2), "r"(a3), "r"(b0), "r"(b1));
}

__device__ __forceinline__ void cp16(uint32_t* dst_smem, const void* src)
{
    uint32_t d = (uint32_t)__cvta_generic_to_shared(dst_smem);
    asm volatile("cp.async.cg.shared.global [%0], [%1], 16;" :: "r"(d), "l"(src));
}
__device__ __forceinline__ void cp_commit() { asm volatile("cp.async.commit_group;" ::: "memory"); }
template<int N>
__device__ __forceinline__ void cp_wait() { asm volatile("cp.async.wait_group %0;" :: "n"(N) : "memory"); }

// ---------------------------------------------------------------------------
// K_pre: pack all weights to half2.
// ---------------------------------------------------------------------------
__global__ void k_roundw(const float* __restrict__ Wq, const float* __restrict__ Wk,
                         const float* __restrict__ Wv, const float* __restrict__ W1,
                         const float* __restrict__ W2)
{
    int i = blockIdx.x * 256 + threadIdx.x;   // 0 .. 65535
    if (i < (CQ * CQ) / 2) {
        __half2 hq = __floats2half2_rn(Wq[2 * i], Wq[2 * i + 1]);
        __half2 hk = __floats2half2_rn(Wk[2 * i], Wk[2 * i + 1]);
        __half2 hv = __floats2half2_rn(Wv[2 * i], Wv[2 * i + 1]);
        g_wqh[i] = *(uint32_t*)&hq;
        g_wkh[i] = *(uint32_t*)&hk;
        g_wvh[i] = *(uint32_t*)&hv;
    }
    if (i < (HIDQ * CQ) / 2) {
        __half2 h1 = __floats2half2_rn(W1[2 * i], W1[2 * i + 1]);
        g_w1h[i] = *(uint32_t*)&h1;
        __half2 h2 = __floats2half2_rn(W2[2 * i], W2[2 * i + 1]);
        g_w2h[i] = *(uint32_t*)&h2;
    }
}

// ---------------------------------------------------------------------------
// K0: transpose x (B,C,P) -> g_xpm (fp32) and g_xh (half2 packed), (B,P,C).
// Also writes out channels 0..3 directly.
// ---------------------------------------------------------------------------
__global__ void k_transpose(const float* __restrict__ x, float* __restrict__ out)
{
    __shared__ float tile[32][33];
    int b = blockIdx.z;
    int p0 = blockIdx.x * 32;
    int c0 = blockIdx.y * 32;
    const float* xb = x + (size_t)b * CQ * PQ;
    int tx = threadIdx.x, ty = threadIdx.y;
#pragma unroll
    for (int i = 0; i < 32; i += 8) {
        float v = xb[(size_t)(c0 + ty + i) * PQ + p0 + tx];
        tile[ty + i][tx] = v;
        if (c0 == 0 && (ty + i) < 4)
            out[(size_t)b * OUTC * PQ + (size_t)(ty + i) * PQ + p0 + tx] = v;
    }
    __syncthreads();
    float* op = g_xpm + (size_t)b * PQ * CQ;
#pragma unroll
    for (int i = 0; i < 32; i += 8) {
        int p = p0 + ty + i;
        op[(size_t)p * CQ + c0 + tx] = tile[tx][ty + i];
        if (tx < 16) {
            __half2 h = __floats2half2_rn(tile[2 * tx][ty + i], tile[2 * tx + 1][ty + i]);
            g_xh[(size_t)(b * PQ + p) * 64 + c0 / 2 + tx] = *(uint32_t*)&h;
        }
    }
}

// ---------------------------------------------------------------------------
// K1: top-K neighbor selection (round-14 exact algorithm; the only change is
// the exhaustion vote hoisted out of the merge loop — conservative-exact).
// ---------------------------------------------------------------------------
__global__ void __launch_bounds__(256) k_topk(const float* __restrict__ x)
{
    int t = blockIdx.x, b = blockIdx.y, z = blockIdx.z;
    __shared__ float sc[3][THREEN];
    const float* xb = x + (size_t)b * CQ * PQ;
    int tid = threadIdx.x;

    for (int i = tid; i < 3 * THREEN; i += 256) {
        int c = i / THREEN, m = i % THREEN;
        int j = m >> 9, nn = m & 511;
        int te = t - 1 + j;
        te = te < 0 ? 0 : (te > TQ - 1 ? TQ - 1 : te);
        sc[c][m] = xb[(size_t)c * PQ + te * NQ + nn];
    }
    __syncthreads();

    const unsigned FULL = 0xffffffffu;
    const float FINF = __int_as_float(0x7f800000);
    int lane = tid & 31, w = tid >> 5;

    for (int i = 0; i < 8; i++) {
        int n = z * 64 + w * 8 + i;
        float a0 = sc[0][512 + n], a1 = sc[1][512 + n], a2 = sc[2][512 + n];

        float e0 = FINF, e1 = FINF, e2 = FINF, e3 = FINF;
        int   q0 = 0,    q1 = 0,    q2 = 0,    q3 = 0;
#pragma unroll
        for (int jj = 0; jj < 48; jj++) {
            int m = jj * 32 + lane;
            float dx = sc[0][m] - a0;
            float dy = sc[1][m] - a1;
            float dz = sc[2][m] - a2;
            float dc = dx * dx + dy * dy + dz * dz;
            bool l0 = dc < e0, l1 = dc < e1, l2 = dc < e2, l3 = dc < e3;
            e3 = l3 ? (l2 ? e2 : dc) : e3;  q3 = l3 ? (l2 ? q2 : m) : q3;
            e2 = l2 ? (l1 ? e1 : dc) : e2;  q2 = l2 ? (l1 ? q1 : m) : q2;
            e1 = l1 ? (l0 ? e0 : dc) : e1;  q1 = l1 ? (l0 ? q0 : m) : q1;
            e0 = l0 ? dc : e0;              q0 = l0 ? m : q0;
        }

        int ptr = 0;
        int* orow = g_idx + ((size_t)(b * TQ + t) * NQ + n) * KQ;
#pragma unroll
        for (int it = 0; it < KQ; it++) {
            unsigned long long mykey =
                ((unsigned long long)__float_as_uint(e0) << 32) | (unsigned)q0;
            unsigned long long k = mykey;
#pragma unroll
            for (int off = 16; off; off >>= 1) {
                unsigned long long o = __shfl_xor_sync(FULL, k, off);
                if (o < k) k = o;
            }
            if (mykey == k) {
                e0 = e1; q0 = q1; e1 = e2; q1 = q2; e2 = e3; q2 = q3;
                e3 = FINF; q3 = 0; ptr++;
            }
            if (lane == 0) {
                int m = (int)(k & 0xffffffffu);
                int jwin = m >> 9, nwin = m & 511;
                int te = t - 1 + jwin;
                te = te < 0 ? 0 : (te > TQ - 1 ? TQ - 1 : te);
                orow[it] = te * NQ + nwin;
            }
        }

        // conservative exhaustion check, hoisted out of the merge loop:
        // any lane that drained its 4 slots MIGHT have owned a later pick.
        if (__any_sync(FULL, ptr >= 4)) {
            unsigned long long removed = 0ull;
            for (int it = 0; it < KQ; it++) {
                float best = 3.4e38f;
                int bj = 0;
#pragma unroll
                for (int jj = 0; jj < 48; jj++) {
                    int m = jj * 32 + lane;
                    float dx = sc[0][m] - a0;
                    float dy = sc[1][m] - a1;
                    float dz = sc[2][m] - a2;
                    float dc = dx * dx + dy * dy + dz * dz;
                    bool alive = !(removed & (1ull << jj));
                    if (alive && dc < best) { best = dc; bj = jj; }
                }
                int bm = bj * 32 + lane;
#pragma unroll
                for (int off = 16; off; off >>= 1) {
                    float od = __shfl_xor_sync(FULL, best, off);
                    int   om = __shfl_xor_sync(FULL, bm, off);
                    if (od < best || (od == best && om < bm)) { best = od; bm = om; }
                }
                if ((bm & 31) == lane) removed |= (1ull << (bm >> 5));
                if (lane == 0) {
                    int jwin = bm >> 9, nwin = bm & 511;
                    int te = t - 1 + jwin;
                    te = te < 0 ? 0 : (te > TQ - 1 ? TQ - 1 : te);
                    orow[it] = te * NQ + nwin;
                }
            }
        }
    }
}

// ---------------------------------------------------------------------------
// Shared fp16 A-resident GEMM pass (unchanged from round 14).
// ---------------------------------------------------------------------------
__device__ __forceinline__ void gemm_f16_Ares_pass(const uint32_t* __restrict__ Ah,
                                                   uint32_t* __restrict__ Bs,
                                                   const uint32_t* __restrict__ Wg,
                                                   float acc[4][4][4], int tid)
{
    const int lane = tid & 31, wid = tid >> 5;
    const int gid = lane >> 2, tig = lane & 3;
    const int mbase = (wid & 1) * 64, nbase = (wid >> 1) * 32;
    const int r0 = tid >> 2, s0 = (tid & 3) * 4;
    const int r1 = r0 + 64;

    cp16(&Bs[r0 * 20 + s0], Wg + (size_t)r0 * 64 + s0);
    cp16(&Bs[r1 * 20 + s0], Wg + (size_t)r1 * 64 + s0);
    cp_commit();

#pragma unroll 1
    for (int kc = 0; kc < 4; kc++) {
        const int st = kc & 1;
        cp_wait<0>();
        __syncthreads();
        if (kc + 1 < 4) {
            const int k0g = (kc + 1) * 16;
            uint32_t* Bd = Bs + (st ^ 1) * (128 * 20);
            cp16(&Bd[r0 * 20 + s0], Wg + (size_t)r0 * 64 + k0g + s0);
            cp16(&Bd[r1 * 20 + s0], Wg + (size_t)r1 * 64 + k0g + s0);
            cp_commit();
        }
        const uint32_t* Bc = Bs + st * (128 * 20);

#pragma unroll
        for (int ks = 0; ks < 2; ks++) {
            const int ka = kc * 16 + ks * 8;
            const int kb = ks * 8;
            uint32_t af[4][4], bf[4][2];
#pragma unroll
            for (int mt = 0; mt < 4; mt++) {
                int m = mbase + mt * 16 + gid;
                af[mt][0] = Ah[m * 68 + ka + tig];
                af[mt][1] = Ah[(m + 8) * 68 + ka + tig];
                af[mt][2] = Ah[m * 68 + ka + 4 + tig];
                af[mt][3] = Ah[(m + 8) * 68 + ka + 4 + tig];
            }
#pragma unroll
            for (int nt = 0; nt < 4; nt++) {
                int n = nbase + nt * 8 + gid;
                bf[nt][0] = Bc[n * 20 + kb + tig];
                bf[nt][1] = Bc[n * 20 + kb + 4 + tig];
            }
#pragma unroll
            for (int mt = 0; mt < 4; mt++)
#pragma unroll
                for (int nt = 0; nt < 4; nt++)
                    mma_f16(acc[mt][nt], af[mt][0], af[mt][1], af[mt][2], af[mt][3],
                            bf[nt][0], bf[nt][1]);
        }
    }
}

#define F16_ARES_SMEM ((128 * 68 + 2 * 128 * 20) * 4)   // 55296 B

// K2: merged QKV projection, full fp16 (unchanged from round 14).
__global__ void __launch_bounds__(256) k_gemm_qkv()
{
    extern __shared__ uint32_t sm[];
    uint32_t* Ah = sm;                    // [128][68]
    uint32_t* Bs = sm + 128 * 68;         // [2][128][20]

    const int b = blockIdx.y;
    const int p0 = blockIdx.x * 128;
    const int tid = threadIdx.x;
    const uint32_t* A = g_xh + (size_t)(b * PQ + p0) * 64;

#pragma unroll
    for (int it = 0; it < 8; it++) {
        int id = tid + it * 256;
        int r = id >> 4, seg = (id & 15) * 4;
        cp16(&Ah[r * 68 + seg], A + (size_t)r * 64 + seg);
    }
    cp_commit();

    const int lane = tid & 31, wid = tid >> 5;
    const int gid = lane >> 2, tig = lane & 3;

#pragma unroll 1
    for (int cq = 0; cq < 3; cq++) {
        const uint32_t* Wg = (cq == 0) ? g_wqh : ((cq == 1) ? g_wkh : g_wvh);
        float acc[4][4][4] = {};
        gemm_f16_Ares_pass(Ah, Bs, Wg, acc, tid);

        const int prow = b * PQ + p0 + (wid & 1) * 64;
        if (cq == 0) {
            float* base = g_q + (size_t)prow * CQ + (wid >> 1) * 32;
#pragma unroll
            for (int mt = 0; mt < 4; mt++) {
                int r = mt * 16 + gid;
#pragma unroll
                for (int nt = 0; nt < 4; nt++) {
                    int c = nt * 8 + tig * 2;
                    *(float2*)(base + (size_t)r * CQ + c)       = make_float2(acc[mt][nt][0], acc[mt][nt][1]);
                    *(float2*)(base + (size_t)(r + 8) * CQ + c) = make_float2(acc[mt][nt][2], acc[mt][nt][3]);
                }
            }
        } else {
            uint32_t* base = g_kvh + (size_t)prow * 128 + (cq - 1) * 64 + (wid >> 1) * 16;
#pragma unroll
            for (int mt = 0; mt < 4; mt++) {
                int r = mt * 16 + gid;
#pragma unroll
                for (int nt = 0; nt < 4; nt++) {
                    int h2i = nt * 4 + tig;
                    __half2 lo = __floats2half2_rn(acc[mt][nt][0], acc[mt][nt][1]);
                    __half2 hi = __floats2half2_rn(acc[mt][nt][2], acc[mt][nt][3]);
                    base[(size_t)r * 128 + h2i]       = *(uint32_t*)&lo;
                    base[(size_t)(r + 8) * 128 + h2i] = *(uint32_t*)&hi;
                }
            }
        }
    }
}

// ---------------------------------------------------------------------------
// K3: attention + residual + BN (unchanged from round 14).
// ---------------------------------------------------------------------------
__global__ void __launch_bounds__(256) k_attn(const float* __restrict__ gamma,
                                              const float* __restrict__ beta,
                                              const float* __restrict__ mean,
                                              const float* __restrict__ var)
{
    __shared__ float s_scale[CQ], s_shift[CQ];
    int tid = threadIdx.x;
    if (tid < CQ) {
        float sc = gamma[tid] * rsqrtf(var[tid] + 1e-5f);
        s_scale[tid] = sc;
        s_shift[tid] = beta[tid] - mean[tid] * sc;
    }
    __syncthreads();

    int lane = tid & 31, w = tid >> 5;
    const float rs = 0.17677669529663687f; // 1/sqrt(32)

    for (int i = 0; i < 8; i++) {
        int g = blockIdx.x * 64 + w * 8 + i;
        int b = g >> 14;
        int bbase = b << 14;

        float4 qv = ((const float4*)(g_q + (size_t)g * CQ))[lane];

        const uint32_t* kvrow = g_kvh + (size_t)g * 128;
        uint2 su = *(const uint2*)(kvrow + 2 * lane);
        uint2 vu = *(const uint2*)(kvrow + 64 + 2 * lane);
        float2 k0 = __half22float2(*(__half2*)&su.x);
        float2 k1 = __half22float2(*(__half2*)&su.y);
        float2 v0 = __half22float2(*(__half2*)&vu.x);
        float2 v1 = __half22float2(*(__half2*)&vu.y);

        const int* irow = g_idx + (size_t)g * KQ;
        int myidx = irow[lane & 15];

        float dself;
        {
            float p = qv.x * k0.x + qv.y * k0.y + qv.z * k1.x + qv.w * k1.y;
            p += __shfl_xor_sync(0xffffffffu, p, 1);
            p += __shfl_xor_sync(0xffffffffu, p, 2);
            p += __shfl_xor_sync(0xffffffffu, p, 4);
            dself = p;
        }

        float e[16];
#pragma unroll
        for (int k = 0; k < 16; k++) {
            int nb = __shfl_sync(0xffffffffu, myidx, k);
            uint2 ku = *(const uint2*)(g_kvh + (size_t)(bbase + nb) * 128 + 2 * lane);
            float2 f0 = __half22float2(*(__half2*)&ku.x);
            float2 f1 = __half22float2(*(__half2*)&ku.y);
            float p = qv.x * f0.x + qv.y * f0.y + qv.z * f1.x + qv.w * f1.y;
            p += __shfl_xor_sync(0xffffffffu, p, 1);
            p += __shfl_xor_sync(0xffffffffu, p, 2);
            p += __shfl_xor_sync(0xffffffffu, p, 4);
            e[k] = (dself - p) * rs;
        }

        float mx = e[0];
#pragma unroll
        for (int k = 1; k < 16; k++) mx = fmaxf(mx, e[k]);
        float s = 0.f;
#pragma unroll
        for (int k = 0; k < 16; k++) { e[k] = __expf(e[k] - mx); s += e[k]; }
        float inv = 1.0f / s;

        float4 acc = make_float4(v0.x, v0.y, v1.x, v1.y);
#pragma unroll
        for (int k = 0; k < 16; k++) {
            int nb = __shfl_sync(0xffffffffu, myidx, k);
            uint2 wu = *(const uint2*)(g_kvh + (size_t)(bbase + nb) * 128 + 64 + 2 * lane);
            float2 f0 = __half22float2(*(__half2*)&wu.x);
            float2 f1 = __half22float2(*(__half2*)&wu.y);
            float a = e[k] * inv;
            acc.x -= a * f0.x; acc.y -= a * f0.y;
            acc.z -= a * f1.x; acc.w -= a * f1.y;
        }

        const float4* xp = (const float4*)(g_xpm + (size_t)g * CQ);
        float4 xv = xp[lane];
        int c = lane * 4;
        float h0 = (xv.x + acc.x) * s_scale[c + 0] + s_shift[c + 0];
        float h1 = (xv.y + acc.y) * s_scale[c + 1] + s_shift[c + 1];
        float h2 = (xv.z + acc.z) * s_scale[c + 2] + s_shift[c + 2];
        float h3 = (xv.w + acc.w) * s_scale[c + 3] + s_shift[c + 3];
        __half2 lo = __floats2half2_rn(h0, h1);
        __half2 hi = __floats2half2_rn(h2, h3);
        ((uint2*)(g_hh + (size_t)g * 64))[lane] = make_uint2(*(uint32_t*)&lo, *(uint32_t*)&hi);
    }
}

// ---------------------------------------------------------------------------
// K4: hid = leaky(W1 @ h), fp16 (unchanged from round 14). grid (PQ/128, B).
// ---------------------------------------------------------------------------
__global__ void __launch_bounds__(256) k_gemm_w1()
{
    extern __shared__ uint32_t sm[];
    uint32_t* Ah = sm;                    // [128][68]
    uint32_t* Bs = sm + 128 * 68;         // [2][128][20]

    const int b = blockIdx.y;
    const int p0 = blockIdx.x * 128;
    const int tid = threadIdx.x;
    const uint32_t* A = g_hh + (size_t)(b * PQ + p0) * 64;

#pragma unroll
    for (int it = 0; it < 8; it++) {
        int id = tid + it * 256;
        int r = id >> 4, seg = (id & 15) * 4;
        cp16(&Ah[r * 68 + seg], A + (size_t)r * 64 + seg);
    }
    cp_commit();

    const int lane = tid & 31, wid = tid >> 5;
    const int gid = lane >> 2, tig = lane & 3;

#pragma unroll 1
    for (int nt4 = 0; nt4 < 4; nt4++) {
        const int co0 = nt4 * 128;
        float acc[4][4][4] = {};
        gemm_f16_Ares_pass(Ah, Bs, g_w1h + (size_t)co0 * 64, acc, tid);

        uint32_t* base = g_hidh + (size_t)(b * PQ + p0 + (wid & 1) * 64) * (HIDQ / 2)
                       + co0 / 2 + (wid >> 1) * 16;
#pragma unroll
        for (int mt = 0; mt < 4; mt++) {
            int r = mt * 16 + gid;
#pragma unroll
            for (int nt = 0; nt < 4; nt++) {
                int h2i = nt * 4 + tig;
                float v0 = acc[mt][nt][0], v1 = acc[mt][nt][1];
                float v2 = acc[mt][nt][2], v3 = acc[mt][nt][3];
                v0 = v0 > 0.f ? v0 : 0.2f * v0;
                v1 = v1 > 0.f ? v1 : 0.2f * v1;
                v2 = v2 > 0.f ? v2 : 0.2f * v2;
                v3 = v3 > 0.f ? v3 : 0.2f * v3;
                __half2 lo = __floats2half2_rn(v0, v1);
                __half2 hi = __floats2half2_rn(v2, v3);
                base[(size_t)r * (HIDQ / 2) + h2i]       = *(uint32_t*)&lo;
                base[(size_t)(r + 8) * (HIDQ / 2) + h2i] = *(uint32_t*)&hi;
            }
        }
    }
}

// ---------------------------------------------------------------------------
// K5: y = W2 @ hid, fp16 streaming (unchanged from round 14).
// ---------------------------------------------------------------------------
__global__ void __launch_bounds__(256) k_gemm_w2(float* __restrict__ out)
{
    __shared__ uint32_t As[2][128 * 20];
    __shared__ uint32_t Bs[2][128 * 20];

    const int b = blockIdx.z;
    const int p0 = blockIdx.x * 128;
    const int tid = threadIdx.x;
    const uint32_t* Ag = g_hidh + (size_t)(b * PQ + p0) * (HIDQ / 2);

    const int lane = tid & 31, wid = tid >> 5;
    const int gid = lane >> 2, tig = lane & 3;
    const int mbase = (wid & 1) * 64, nbase = (wid >> 1) * 32;
    const int r0 = tid >> 2, s0 = (tid & 3) * 4;
    const int r1 = r0 + 64;

    float acc[4][4][4] = {};

    cp16(&As[0][r0 * 20 + s0], Ag + (size_t)r0 * (HIDQ / 2) + s0);
    cp16(&As[0][r1 * 20 + s0], Ag + (size_t)r1 * (HIDQ / 2) + s0);
    cp16(&Bs[0][r0 * 20 + s0], g_w2h + (size_t)r0 * (HIDQ / 2) + s0);
    cp16(&Bs[0][r1 * 20 + s0], g_w2h + (size_t)r1 * (HIDQ / 2) + s0);
    cp_commit();

#pragma unroll 1
    for (int kc = 0; kc < 16; kc++) {
        const int st = kc & 1;
        cp_wait<0>();
        __syncthreads();
        if (kc + 1 < 16) {
            const int k0g = (kc + 1) * 16;
            cp16(&As[st ^ 1][r0 * 20 + s0], Ag + (size_t)r0 * (HIDQ / 2) + k0g + s0);
            cp16(&As[st ^ 1][r1 * 20 + s0], Ag + (size_t)r1 * (HIDQ / 2) + k0g + s0);
            cp16(&Bs[st ^ 1][r0 * 20 + s0], g_w2h + (size_t)r0 * (HIDQ / 2) + k0g + s0);
            cp16(&Bs[st ^ 1][r1 * 20 + s0], g_w2h + (size_t)r1 * (HIDQ / 2) + k0g + s0);
            cp_commit();
        }

#pragma unroll
        for (int ks = 0; ks < 2; ks++) {
            const int k0 = ks * 8;
            uint32_t af[4][4], bf[4][2];
#pragma unroll
            for (int mt = 0; mt < 4; mt++) {
                int m = mbase + mt * 16 + gid;
                af[mt][0] = As[st][m * 20 + k0 + tig];
                af[mt][1] = As[st][(m + 8) * 20 + k0 + tig];
                af[mt][2] = As[st][m * 20 + k0 + 4 + tig];
                af[mt][3] = As[st][(m + 8) * 20 + k0 + 4 + tig];
            }
#pragma unroll
            for (int nt = 0; nt < 4; nt++) {
                int n = nbase + nt * 8 + gid;
                bf[nt][0] = Bs[st][n * 20 + k0 + tig];
                bf[nt][1] = Bs[st][n * 20 + k0 + 4 + tig];
            }
#pragma unroll
            for (int mt = 0; mt < 4; mt++)
#pragma unroll
                for (int nt = 0; nt < 4; nt++)
                    mma_f16(acc[mt][nt], af[mt][0], af[mt][1], af[mt][2], af[mt][3],
                            bf[nt][0], bf[nt][1]);
        }
    }

    float* ob = out + (size_t)b * OUTC * PQ + (size_t)4 * PQ;
    int rbase = p0 + mbase;
#pragma unroll
    for (int mt = 0; mt < 4; mt++) {
        int r = rbase + mt * 16 + gid;
#pragma unroll
        for (int nt = 0; nt < 4; nt++) {
            int c = nbase + nt * 8 + tig * 2;
            ob[(size_t)c * PQ + r]           = acc[mt][nt][0];
            ob[(size_t)(c + 1) * PQ + r]     = acc[mt][nt][1];
            ob[(size_t)c * PQ + r + 8]       = acc[mt][nt][2];
            ob[(size_t)(c + 1) * PQ + r + 8] = acc[mt][nt][3];
        }
    }
}

// ---------------------------------------------------------------------------
extern "C" void kernel_launch(void* const* d_in, const int* in_sizes, int n_in,
                              void* d_out, int out_size)
{
    const float* x     = (const float*)d_in[0];
    const float* Wq    = (const float*)d_in[1];
    const float* Wk    = (const float*)d_in[2];
    const float* Wv    = (const float*)d_in[3];
    const float* W1    = (const float*)d_in[4];
    const float* W2    = (const float*)d_in[5];
    const float* gamma = (const float*)d_in[6];
    const float* beta  = (const float*)d_in[7];
    const float* mean  = (const float*)d_in[8];
    const float* var   = (const float*)d_in[9];
    float* out = (float*)d_out;

    static cudaStream_t s2;
    static cudaEvent_t evFork, evJoin;
    static int init_done = 0;
    if (!init_done) {
        cudaFuncSetAttribute(k_gemm_qkv, cudaFuncAttributeMaxDynamicSharedMemorySize, F16_ARES_SMEM);
        cudaFuncSetAttribute(k_gemm_w1,  cudaFuncAttributeMaxDynamicSharedMemorySize, F16_ARES_SMEM);
        cudaStreamCreateWithFlags(&s2, cudaStreamNonBlocking);
        cudaEventCreateWithFlags(&evFork, cudaEventDisableTiming);
        cudaEventCreateWithFlags(&evJoin, cudaEventDisableTiming);
        init_done = 1;
    }

    // Round-8 structure: single fork for topk, everything else serial full-grid.
    cudaEventRecord(evFork, 0);
    cudaStreamWaitEvent(s2, evFork, 0);
    k_topk<<<dim3(TQ, BQ, 8), 256, 0, s2>>>(x);
    cudaEventRecord(evJoin, s2);

    k_roundw<<<256, 256>>>(Wq, Wk, Wv, W1, W2);
    k_transpose<<<dim3(PQ / 32, CQ / 32, BQ), dim3(32, 8)>>>(x, out);
    k_gemm_qkv<<<dim3(PQ / 128, BQ), 256, F16_ARES_SMEM>>>();

    cudaStreamWaitEvent(0, evJoin, 0);
    k_attn<<<dim3((BQ * PQ) / 64, 1, 1), 256>>>(gamma, beta, mean, var);
    k_gemm_w1<<<dim3(PQ / 128, BQ), 256, F16_ARES_SMEM>>>();
    k_gemm_w2<<<dim3(PQ / 128, 1, BQ), 256>>>(out);
}

// round 17
// speedup vs baseline: 1.5646x; 1.0557x over previous
#include <cuda_runtime.h>
#include <cuda_fp16.h>
#include <math.h>
#include <stdint.h>

// Problem constants
#define BQ 2
#define CQ 128
#define TQ 32
#define NQ 512
#define PQ (TQ * NQ)      // 16384 points per batch
#define KQ 16
#define HIDQ 512
#define OUTC 132
#define THREEN 1536

// ---------------------------------------------------------------------------
// Device scratch (static — no allocations allowed)
// ---------------------------------------------------------------------------
__device__ float    g_xpm[BQ * PQ * CQ];   // x transposed (b,p,c), full precision (residual)
__device__ uint32_t g_xh[BQ * PQ * 64];    // x transposed, half2 packed (QKV input)
__device__ float    g_q[BQ * PQ * CQ];     // q projection, fp32, point-major
__device__ uint32_t g_kvh[BQ * PQ * 128];  // per point: [0..63] kx half2, [64..127] vx half2
__device__ int      g_idx[BQ * PQ * KQ];   // neighbor composite index t_eff*N + n'
__device__ uint32_t g_hh[BQ * PQ * 64];    // post-attn+BN h, half2 packed (W1 input)
__device__ uint32_t g_hidh[BQ * PQ * (HIDQ / 2)];  // leaky(W1@h), half2 packed (W2 input)
__device__ uint32_t g_wqh[(CQ * CQ) / 2];  // Wq half2 packed along k
__device__ uint32_t g_wkh[(CQ * CQ) / 2];  // Wk
__device__ uint32_t g_wvh[(CQ * CQ) / 2];  // Wv
__device__ uint32_t g_w1h[(HIDQ * CQ) / 2];
__device__ uint32_t g_w2h[(CQ * HIDQ) / 2];

// ---------------------------------------------------------------------------
// fp16 / async helpers
// ---------------------------------------------------------------------------
__device__ __forceinline__ void mma_f16(float c[4],
                                        uint32_t a0, uint32_t a1, uint32_t a2, uint32_t a3,
                                        uint32_t b0, uint32_t b1)
{
    asm volatile(
        "mma.sync.aligned.m16n8k16.row.col.f32.f16.f16.f32 "
        "{%0,%1,%2,%3},{%4,%5,%6,%7},{%8,%9},{%0,%1,%2,%3};"
        : "+f"(c[0]), "+f"(c[1]), "+f"(c[2]), "+f"(c[3])
        : "r"(a0), "r"(a1), "r"(a2), "r"(a3), "r"(b0), "r"(b1));
}

__device__ __forceinline__ void cp16(uint32_t* dst_smem, const void* src)
{
    uint32_t d = (uint32_t)__cvta_generic_to_shared(dst_smem);
    asm volatile("cp.async.cg.shared.global [%0], [%1], 16;" :: "r"(d), "l"(src));
}
__device__ __forceinline__ void cp_commit() { asm volatile("cp.async.commit_group;" ::: "memory"); }
template<int N>
__device__ __forceinline__ void cp_wait() { asm volatile("cp.async.wait_group %0;" :: "n"(N) : "memory"); }

__device__ __forceinline__ unsigned long long u64min(unsigned long long a, unsigned long long b)
{
    return a < b ? a : b;
}

// ---------------------------------------------------------------------------
// K_pre: pack all weights to half2.
// ---------------------------------------------------------------------------
__global__ void k_roundw(const float* __restrict__ Wq, const float* __restrict__ Wk,
                         const float* __restrict__ Wv, const float* __restrict__ W1,
                         const float* __restrict__ W2)
{
    int i = blockIdx.x * 256 + threadIdx.x;   // 0 .. 65535
    if (i < (CQ * CQ) / 2) {
        __half2 hq = __floats2half2_rn(Wq[2 * i], Wq[2 * i + 1]);
        __half2 hk = __floats2half2_rn(Wk[2 * i], Wk[2 * i + 1]);
        __half2 hv = __floats2half2_rn(Wv[2 * i], Wv[2 * i + 1]);
        g_wqh[i] = *(uint32_t*)&hq;
        g_wkh[i] = *(uint32_t*)&hk;
        g_wvh[i] = *(uint32_t*)&hv;
    }
    if (i < (HIDQ * CQ) / 2) {
        __half2 h1 = __floats2half2_rn(W1[2 * i], W1[2 * i + 1]);
        g_w1h[i] = *(uint32_t*)&h1;
        __half2 h2 = __floats2half2_rn(W2[2 * i], W2[2 * i + 1]);
        g_w2h[i] = *(uint32_t*)&h2;
    }
}

// ---------------------------------------------------------------------------
// K0: transpose x (B,C,P) -> g_xpm (fp32) and g_xh (half2 packed), (B,P,C).
// Also writes out channels 0..3 directly.
// ---------------------------------------------------------------------------
__global__ void k_transpose(const float* __restrict__ x, float* __restrict__ out)
{
    __shared__ float tile[32][33];
    int b = blockIdx.z;
    int p0 = blockIdx.x * 32;
    int c0 = blockIdx.y * 32;
    const float* xb = x + (size_t)b * CQ * PQ;
    int tx = threadIdx.x, ty = threadIdx.y;
#pragma unroll
    for (int i = 0; i < 32; i += 8) {
        float v = xb[(size_t)(c0 + ty + i) * PQ + p0 + tx];
        tile[ty + i][tx] = v;
        if (c0 == 0 && (ty + i) < 4)
            out[(size_t)b * OUTC * PQ + (size_t)(ty + i) * PQ + p0 + tx] = v;
    }
    __syncthreads();
    float* op = g_xpm + (size_t)b * PQ * CQ;
#pragma unroll
    for (int i = 0; i < 32; i += 8) {
        int p = p0 + ty + i;
        op[(size_t)p * CQ + c0 + tx] = tile[tx][ty + i];
        if (tx < 16) {
            __half2 h = __floats2half2_rn(tile[2 * tx][ty + i], tile[2 * tx + 1][ty + i]);
            g_xh[(size_t)(b * PQ + p) * 64 + c0 / 2 + tx] = *(uint32_t*)&h;
        }
    }
}

// ---------------------------------------------------------------------------
// K1: top-K neighbor selection (exact semantics).
//  - dual independent sorted top-4 insertion chains (even/odd candidates,
//    all scalar registers) for ILP in the 48-candidate scan
//  - exact branchless bitonic merge of the two sorted u64-key lists -> top-4
//  - merge picks via two __reduce_min_sync u32 ops (d-bits, then index among
//    d-winners) — exact (d, m) lexicographic winner, m globally unique
//  - r14 exhaustion semantics: per-lane "exhausted before a pick" flag,
//    single end vote -> exact fallback
// ---------------------------------------------------------------------------
__global__ void __launch_bounds__(256) k_topk(const float* __restrict__ x)
{
    int t = blockIdx.x, b = blockIdx.y, z = blockIdx.z;
    __shared__ float sc[3][THREEN];
    const float* xb = x + (size_t)b * CQ * PQ;
    int tid = threadIdx.x;

    for (int i = tid; i < 3 * THREEN; i += 256) {
        int c = i / THREEN, m = i % THREEN;
        int j = m >> 9, nn = m & 511;
        int te = t - 1 + j;
        te = te < 0 ? 0 : (te > TQ - 1 ? TQ - 1 : te);
        sc[c][m] = xb[(size_t)c * PQ + te * NQ + nn];
    }
    __syncthreads();

    const unsigned FULL = 0xffffffffu;
    const float FINF = __int_as_float(0x7f800000);
    int lane = tid & 31, w = tid >> 5;

    for (int i = 0; i < 8; i++) {
        int n = z * 64 + w * 8 + i;
        float a0 = sc[0][512 + n], a1 = sc[1][512 + n], a2 = sc[2][512 + n];

        // dual insertion chains (even jj -> e/q, odd jj -> f/r), scalar regs only
        float e0 = FINF, e1 = FINF, e2 = FINF, e3 = FINF;
        int   q0 = 0,    q1 = 0,    q2 = 0,    q3 = 0;
        float f0 = FINF, f1 = FINF, f2 = FINF, f3 = FINF;
        int   r0 = 0,    r1 = 0,    r2 = 0,    r3 = 0;
#pragma unroll
        for (int jj = 0; jj < 48; jj += 2) {
            {
                int m = jj * 32 + lane;
                float dx = sc[0][m] - a0;
                float dy = sc[1][m] - a1;
                float dz = sc[2][m] - a2;
                float dc = dx * dx + dy * dy + dz * dz;
                bool l0 = dc < e0, l1 = dc < e1, l2 = dc < e2, l3 = dc < e3;
                e3 = l3 ? (l2 ? e2 : dc) : e3;  q3 = l3 ? (l2 ? q2 : m) : q3;
                e2 = l2 ? (l1 ? e1 : dc) : e2;  q2 = l2 ? (l1 ? q1 : m) : q2;
                e1 = l1 ? (l0 ? e0 : dc) : e1;  q1 = l1 ? (l0 ? q0 : m) : q1;
                e0 = l0 ? dc : e0;              q0 = l0 ? m : q0;
            }
            {
                int m = (jj + 1) * 32 + lane;
                float dx = sc[0][m] - a0;
                float dy = sc[1][m] - a1;
                float dz = sc[2][m] - a2;
                float dc = dx * dx + dy * dy + dz * dz;
                bool l0 = dc < f0, l1 = dc < f1, l2 = dc < f2, l3 = dc < f3;
                f3 = l3 ? (l2 ? f2 : dc) : f3;  r3 = l3 ? (l2 ? r2 : m) : r3;
                f2 = l2 ? (l1 ? f1 : dc) : f2;  r2 = l2 ? (l1 ? r1 : m) : r2;
                f1 = l1 ? (l0 ? f0 : dc) : f1;  r1 = l1 ? (l0 ? r0 : m) : r1;
                f0 = l0 ? dc : f0;              r0 = l0 ? m : r0;
            }
        }

        // exact merge of the two sorted 4-lists -> global top-4 (u64 keys)
        unsigned long long A0 = ((unsigned long long)__float_as_uint(e0) << 32) | (unsigned)q0;
        unsigned long long A1 = ((unsigned long long)__float_as_uint(e1) << 32) | (unsigned)q1;
        unsigned long long A2 = ((unsigned long long)__float_as_uint(e2) << 32) | (unsigned)q2;
        unsigned long long A3 = ((unsigned long long)__float_as_uint(e3) << 32) | (unsigned)q3;
        unsigned long long B0 = ((unsigned long long)__float_as_uint(f0) << 32) | (unsigned)r0;
        unsigned long long B1 = ((unsigned long long)__float_as_uint(f1) << 32) | (unsigned)r1;
        unsigned long long B2 = ((unsigned long long)__float_as_uint(f2) << 32) | (unsigned)r2;
        unsigned long long B3 = ((unsigned long long)__float_as_uint(f3) << 32) | (unsigned)r3;

        unsigned long long s0 = u64min(A0, B3);
        unsigned long long s1 = u64min(A1, B2);
        unsigned long long s2 = u64min(A2, B1);
        unsigned long long s3 = u64min(A3, B0);
        // sort the bitonic 4-sequence
        { unsigned long long tt; if (s2 < s0) { tt = s0; s0 = s2; s2 = tt; }
                                 if (s3 < s1) { tt = s1; s1 = s3; s3 = tt; }
                                 if (s1 < s0) { tt = s0; s0 = s1; s1 = tt; }
                                 if (s3 < s2) { tt = s2; s2 = s3; s3 = tt; } }

        // 16-round merge via REDUX (exact lexicographic winner)
        int ptr = 0;
        bool bad = false;
        int* orow = g_idx + ((size_t)(b * TQ + t) * NQ + n) * KQ;
#pragma unroll
        for (int it = 0; it < KQ; it++) {
            bad |= (ptr >= 4);
            unsigned myd = (unsigned)(s0 >> 32);
            unsigned dmin = __reduce_min_sync(FULL, myd);
            unsigned mym = (myd == dmin) ? (unsigned)s0 : 0xffffffffu;
            unsigned mwin = __reduce_min_sync(FULL, mym);
            if (myd == dmin && (unsigned)s0 == mwin) {
                s0 = s1; s1 = s2; s2 = s3; s3 = ~0ull; ptr++;
            }
            if (lane == 0) {
                int m = (int)mwin;
                int jwin = m >> 9, nwin = m & 511;
                int te = t - 1 + jwin;
                te = te < 0 ? 0 : (te > TQ - 1 ? TQ - 1 : te);
                orow[it] = te * NQ + nwin;
            }
        }

        // r14 semantics: any lane exhausted before some pick -> exact fallback
        if (__any_sync(FULL, bad)) {
            unsigned long long removed = 0ull;
            for (int it = 0; it < KQ; it++) {
                float best = 3.4e38f;
                int bj = 0;
#pragma unroll
                for (int jj = 0; jj < 48; jj++) {
                    int m = jj * 32 + lane;
                    float dx = sc[0][m] - a0;
                    float dy = sc[1][m] - a1;
                    float dz = sc[2][m] - a2;
                    float dc = dx * dx + dy * dy + dz * dz;
                    bool alive = !(removed & (1ull << jj));
                    if (alive && dc < best) { best = dc; bj = jj; }
                }
                int bm = bj * 32 + lane;
#pragma unroll
                for (int off = 16; off; off >>= 1) {
                    float od = __shfl_xor_sync(FULL, best, off);
                    int   om = __shfl_xor_sync(FULL, bm, off);
                    if (od < best || (od == best && om < bm)) { best = od; bm = om; }
                }
                if ((bm & 31) == lane) removed |= (1ull << (bm >> 5));
                if (lane == 0) {
                    int jwin = bm >> 9, nwin = bm & 511;
                    int te = t - 1 + jwin;
                    te = te < 0 ? 0 : (te > TQ - 1 ? TQ - 1 : te);
                    orow[it] = te * NQ + nwin;
                }
            }
        }
    }
}

// ---------------------------------------------------------------------------
// Shared fp16 A-resident GEMM pass (unchanged from round 14).
// ---------------------------------------------------------------------------
__device__ __forceinline__ void gemm_f16_Ares_pass(const uint32_t* __restrict__ Ah,
                                                   uint32_t* __restrict__ Bs,
                                                   const uint32_t* __restrict__ Wg,
                                                   float acc[4][4][4], int tid)
{
    const int lane = tid & 31, wid = tid >> 5;
    const int gid = lane >> 2, tig = lane & 3;
    const int mbase = (wid & 1) * 64, nbase = (wid >> 1) * 32;
    const int r0 = tid >> 2, s0 = (tid & 3) * 4;
    const int r1 = r0 + 64;

    cp16(&Bs[r0 * 20 + s0], Wg + (size_t)r0 * 64 + s0);
    cp16(&Bs[r1 * 20 + s0], Wg + (size_t)r1 * 64 + s0);
    cp_commit();

#pragma unroll 1
    for (int kc = 0; kc < 4; kc++) {
        const int st = kc & 1;
        cp_wait<0>();
        __syncthreads();
        if (kc + 1 < 4) {
            const int k0g = (kc + 1) * 16;
            uint32_t* Bd = Bs + (st ^ 1) * (128 * 20);
            cp16(&Bd[r0 * 20 + s0], Wg + (size_t)r0 * 64 + k0g + s0);
            cp16(&Bd[r1 * 20 + s0], Wg + (size_t)r1 * 64 + k0g + s0);
            cp_commit();
        }
        const uint32_t* Bc = Bs + st * (128 * 20);

#pragma unroll
        for (int ks = 0; ks < 2; ks++) {
            const int ka = kc * 16 + ks * 8;
            const int kb = ks * 8;
            uint32_t af[4][4], bf[4][2];
#pragma unroll
            for (int mt = 0; mt < 4; mt++) {
                int m = mbase + mt * 16 + gid;
                af[mt][0] = Ah[m * 68 + ka + tig];
                af[mt][1] = Ah[(m + 8) * 68 + ka + tig];
                af[mt][2] = Ah[m * 68 + ka + 4 + tig];
                af[mt][3] = Ah[(m + 8) * 68 + ka + 4 + tig];
            }
#pragma unroll
            for (int nt = 0; nt < 4; nt++) {
                int n = nbase + nt * 8 + gid;
                bf[nt][0] = Bc[n * 20 + kb + tig];
                bf[nt][1] = Bc[n * 20 + kb + 4 + tig];
            }
#pragma unroll
            for (int mt = 0; mt < 4; mt++)
#pragma unroll
                for (int nt = 0; nt < 4; nt++)
                    mma_f16(acc[mt][nt], af[mt][0], af[mt][1], af[mt][2], af[mt][3],
                            bf[nt][0], bf[nt][1]);
        }
    }
}

#define F16_ARES_SMEM ((128 * 68 + 2 * 128 * 20) * 4)   // 55296 B

// K2: merged QKV projection, full fp16 (unchanged from round 14).
__global__ void __launch_bounds__(256) k_gemm_qkv()
{
    extern __shared__ uint32_t sm[];
    uint32_t* Ah = sm;                    // [128][68]
    uint32_t* Bs = sm + 128 * 68;         // [2][128][20]

    const int b = blockIdx.y;
    const int p0 = blockIdx.x * 128;
    const int tid = threadIdx.x;
    const uint32_t* A = g_xh + (size_t)(b * PQ + p0) * 64;

#pragma unroll
    for (int it = 0; it < 8; it++) {
        int id = tid + it * 256;
        int r = id >> 4, seg = (id & 15) * 4;
        cp16(&Ah[r * 68 + seg], A + (size_t)r * 64 + seg);
    }
    cp_commit();

    const int lane = tid & 31, wid = tid >> 5;
    const int gid = lane >> 2, tig = lane & 3;

#pragma unroll 1
    for (int cq = 0; cq < 3; cq++) {
        const uint32_t* Wg = (cq == 0) ? g_wqh : ((cq == 1) ? g_wkh : g_wvh);
        float acc[4][4][4] = {};
        gemm_f16_Ares_pass(Ah, Bs, Wg, acc, tid);

        const int prow = b * PQ + p0 + (wid & 1) * 64;
        if (cq == 0) {
            float* base = g_q + (size_t)prow * CQ + (wid >> 1) * 32;
#pragma unroll
            for (int mt = 0; mt < 4; mt++) {
                int r = mt * 16 + gid;
#pragma unroll
                for (int nt = 0; nt < 4; nt++) {
                    int c = nt * 8 + tig * 2;
                    *(float2*)(base + (size_t)r * CQ + c)       = make_float2(acc[mt][nt][0], acc[mt][nt][1]);
                    *(float2*)(base + (size_t)(r + 8) * CQ + c) = make_float2(acc[mt][nt][2], acc[mt][nt][3]);
                }
            }
        } else {
            uint32_t* base = g_kvh + (size_t)prow * 128 + (cq - 1) * 64 + (wid >> 1) * 16;
#pragma unroll
            for (int mt = 0; mt < 4; mt++) {
                int r = mt * 16 + gid;
#pragma unroll
                for (int nt = 0; nt < 4; nt++) {
                    int h2i = nt * 4 + tig;
                    __half2 lo = __floats2half2_rn(acc[mt][nt][0], acc[mt][nt][1]);
                    __half2 hi = __floats2half2_rn(acc[mt][nt][2], acc[mt][nt][3]);
                    base[(size_t)r * 128 + h2i]       = *(uint32_t*)&lo;
                    base[(size_t)(r + 8) * 128 + h2i] = *(uint32_t*)&hi;
                }
            }
        }
    }
}

// ---------------------------------------------------------------------------
// K3: attention + residual + BN (unchanged from round 14).
// ---------------------------------------------------------------------------
__global__ void __launch_bounds__(256) k_attn(const float* __restrict__ gamma,
                                              const float* __restrict__ beta,
                                              const float* __restrict__ mean,
                                              const float* __restrict__ var)
{
    __shared__ float s_scale[CQ], s_shift[CQ];
    int tid = threadIdx.x;
    if (tid < CQ) {
        float sc = gamma[tid] * rsqrtf(var[tid] + 1e-5f);
        s_scale[tid] = sc;
        s_shift[tid] = beta[tid] - mean[tid] * sc;
    }
    __syncthreads();

    int lane = tid & 31, w = tid >> 5;
    const float rs = 0.17677669529663687f; // 1/sqrt(32)

    for (int i = 0; i < 8; i++) {
        int g = blockIdx.x * 64 + w * 8 + i;
        int b = g >> 14;
        int bbase = b << 14;

        float4 qv = ((const float4*)(g_q + (size_t)g * CQ))[lane];

        const uint32_t* kvrow = g_kvh + (size_t)g * 128;
        uint2 su = *(const uint2*)(kvrow + 2 * lane);
        uint2 vu = *(const uint2*)(kvrow + 64 + 2 * lane);
        float2 k0 = __half22float2(*(__half2*)&su.x);
        float2 k1 = __half22float2(*(__half2*)&su.y);
        float2 v0 = __half22float2(*(__half2*)&vu.x);
        float2 v1 = __half22float2(*(__half2*)&vu.y);

        const int* irow = g_idx + (size_t)g * KQ;
        int myidx = irow[lane & 15];

        float dself;
        {
            float p = qv.x * k0.x + qv.y * k0.y + qv.z * k1.x + qv.w * k1.y;
            p += __shfl_xor_sync(0xffffffffu, p, 1);
            p += __shfl_xor_sync(0xffffffffu, p, 2);
            p += __shfl_xor_sync(0xffffffffu, p, 4);
            dself = p;
        }

        float e[16];
#pragma unroll
        for (int k = 0; k < 16; k++) {
            int nb = __shfl_sync(0xffffffffu, myidx, k);
            uint2 ku = *(const uint2*)(g_kvh + (size_t)(bbase + nb) * 128 + 2 * lane);
            float2 f0 = __half22float2(*(__half2*)&ku.x);
            float2 f1 = __half22float2(*(__half2*)&ku.y);
            float p = qv.x * f0.x + qv.y * f0.y + qv.z * f1.x + qv.w * f1.y;
            p += __shfl_xor_sync(0xffffffffu, p, 1);
            p += __shfl_xor_sync(0xffffffffu, p, 2);
            p += __shfl_xor_sync(0xffffffffu, p, 4);
            e[k] = (dself - p) * rs;
        }

        float mx = e[0];
#pragma unroll
        for (int k = 1; k < 16; k++) mx = fmaxf(mx, e[k]);
        float s = 0.f;
#pragma unroll
        for (int k = 0; k < 16; k++) { e[k] = __expf(e[k] - mx); s += e[k]; }
        float inv = 1.0f / s;

        float4 acc = make_float4(v0.x, v0.y, v1.x, v1.y);
#pragma unroll
        for (int k = 0; k < 16; k++) {
            int nb = __shfl_sync(0xffffffffu, myidx, k);
            uint2 wu = *(const uint2*)(g_kvh + (size_t)(bbase + nb) * 128 + 64 + 2 * lane);
            float2 f0 = __half22float2(*(__half2*)&wu.x);
            float2 f1 = __half22float2(*(__half2*)&wu.y);
            float a = e[k] * inv;
            acc.x -= a * f0.x; acc.y -= a * f0.y;
            acc.z -= a * f1.x; acc.w -= a * f1.y;
        }

        const float4* xp = (const float4*)(g_xpm + (size_t)g * CQ);
        float4 xv = xp[lane];
        int c = lane * 4;
        float h0 = (xv.x + acc.x) * s_scale[c + 0] + s_shift[c + 0];
        float h1 = (xv.y + acc.y) * s_scale[c + 1] + s_shift[c + 1];
        float h2 = (xv.z + acc.z) * s_scale[c + 2] + s_shift[c + 2];
        float h3 = (xv.w + acc.w) * s_scale[c + 3] + s_shift[c + 3];
        __half2 lo = __floats2half2_rn(h0, h1);
        __half2 hi = __floats2half2_rn(h2, h3);
        ((uint2*)(g_hh + (size_t)g * 64))[lane] = make_uint2(*(uint32_t*)&lo, *(uint32_t*)&hi);
    }
}

// ---------------------------------------------------------------------------
// K4: hid = leaky(W1 @ h), fp16 (unchanged from round 14). grid (PQ/128, B).
// ---------------------------------------------------------------------------
__global__ void __launch_bounds__(256) k_gemm_w1()
{
    extern __shared__ uint32_t sm[];
    uint32_t* Ah = sm;                    // [128][68]
    uint32_t* Bs = sm + 128 * 68;         // [2][128][20]

    const int b = blockIdx.y;
    const int p0 = blockIdx.x * 128;
    const int tid = threadIdx.x;
    const uint32_t* A = g_hh + (size_t)(b * PQ + p0) * 64;

#pragma unroll
    for (int it = 0; it < 8; it++) {
        int id = tid + it * 256;
        int r = id >> 4, seg = (id & 15) * 4;
        cp16(&Ah[r * 68 + seg], A + (size_t)r * 64 + seg);
    }
    cp_commit();

    const int lane = tid & 31, wid = tid >> 5;
    const int gid = lane >> 2, tig = lane & 3;

#pragma unroll 1
    for (int nt4 = 0; nt4 < 4; nt4++) {
        const int co0 = nt4 * 128;
        float acc[4][4][4] = {};
        gemm_f16_Ares_pass(Ah, Bs, g_w1h + (size_t)co0 * 64, acc, tid);

        uint32_t* base = g_hidh + (size_t)(b * PQ + p0 + (wid & 1) * 64) * (HIDQ / 2)
                       + co0 / 2 + (wid >> 1) * 16;
#pragma unroll
        for (int mt = 0; mt < 4; mt++) {
            int r = mt * 16 + gid;
#pragma unroll
            for (int nt = 0; nt < 4; nt++) {
                int h2i = nt * 4 + tig;
                float v0 = acc[mt][nt][0], v1 = acc[mt][nt][1];
                float v2 = acc[mt][nt][2], v3 = acc[mt][nt][3];
                v0 = v0 > 0.f ? v0 : 0.2f * v0;
                v1 = v1 > 0.f ? v1 : 0.2f * v1;
                v2 = v2 > 0.f ? v2 : 0.2f * v2;
                v3 = v3 > 0.f ? v3 : 0.2f * v3;
                __half2 lo = __floats2half2_rn(v0, v1);
                __half2 hi = __floats2half2_rn(v2, v3);
                base[(size_t)r * (HIDQ / 2) + h2i]       = *(uint32_t*)&lo;
                base[(size_t)(r + 8) * (HIDQ / 2) + h2i] = *(uint32_t*)&hi;
            }
        }
    }
}

// ---------------------------------------------------------------------------
// K5: y = W2 @ hid, fp16 streaming (unchanged from round 14).
// ---------------------------------------------------------------------------
__global__ void __launch_bounds__(256) k_gemm_w2(float* __restrict__ out)
{
    __shared__ uint32_t As[2][128 * 20];
    __shared__ uint32_t Bs[2][128 * 20];

    const int b = blockIdx.z;
    const int p0 = blockIdx.x * 128;
    const int tid = threadIdx.x;
    const uint32_t* Ag = g_hidh + (size_t)(b * PQ + p0) * (HIDQ / 2);

    const int lane = tid & 31, wid = tid >> 5;
    const int gid = lane >> 2, tig = lane & 3;
    const int mbase = (wid & 1) * 64, nbase = (wid >> 1) * 32;
    const int r0 = tid >> 2, s0 = (tid & 3) * 4;
    const int r1 = r0 + 64;

    float acc[4][4][4] = {};

    cp16(&As[0][r0 * 20 + s0], Ag + (size_t)r0 * (HIDQ / 2) + s0);
    cp16(&As[0][r1 * 20 + s0], Ag + (size_t)r1 * (HIDQ / 2) + s0);
    cp16(&Bs[0][r0 * 20 + s0], g_w2h + (size_t)r0 * (HIDQ / 2) + s0);
    cp16(&Bs[0][r1 * 20 + s0], g_w2h + (size_t)r1 * (HIDQ / 2) + s0);
    cp_commit();

#pragma unroll 1
    for (int kc = 0; kc < 16; kc++) {
        const int st = kc & 1;
        cp_wait<0>();
        __syncthreads();
        if (kc + 1 < 16) {
            const int k0g = (kc + 1) * 16;
            cp16(&As[st ^ 1][r0 * 20 + s0], Ag + (size_t)r0 * (HIDQ / 2) + k0g + s0);
            cp16(&As[st ^ 1][r1 * 20 + s0], Ag + (size_t)r1 * (HIDQ / 2) + k0g + s0);
            cp16(&Bs[st ^ 1][r0 * 20 + s0], g_w2h + (size_t)r0 * (HIDQ / 2) + k0g + s0);
            cp16(&Bs[st ^ 1][r1 * 20 + s0], g_w2h + (size_t)r1 * (HIDQ / 2) + k0g + s0);
            cp_commit();
        }

#pragma unroll
        for (int ks = 0; ks < 2; ks++) {
            const int k0 = ks * 8;
            uint32_t af[4][4], bf[4][2];
#pragma unroll
            for (int mt = 0; mt < 4; mt++) {
                int m = mbase + mt * 16 + gid;
                af[mt][0] = As[st][m * 20 + k0 + tig];
                af[mt][1] = As[st][(m + 8) * 20 + k0 + tig];
                af[mt][2] = As[st][m * 20 + k0 + 4 + tig];
                af[mt][3] = As[st][(m + 8) * 20 + k0 + 4 + tig];
            }
#pragma unroll
            for (int nt = 0; nt < 4; nt++) {
                int n = nbase + nt * 8 + gid;
                bf[nt][0] = Bs[st][n * 20 + k0 + tig];
                bf[nt][1] = Bs[st][n * 20 + k0 + 4 + tig];
            }
#pragma unroll
            for (int mt = 0; mt < 4; mt++)
#pragma unroll
                for (int nt = 0; nt < 4; nt++)
                    mma_f16(acc[mt][nt], af[mt][0], af[mt][1], af[mt][2], af[mt][3],
                            bf[nt][0], bf[nt][1]);
        }
    }

    float* ob = out + (size_t)b * OUTC * PQ + (size_t)4 * PQ;
    int rbase = p0 + mbase;
#pragma unroll
    for (int mt = 0; mt < 4; mt++) {
        int r = rbase + mt * 16 + gid;
#pragma unroll
        for (int nt = 0; nt < 4; nt++) {
            int c = nbase + nt * 8 + tig * 2;
            ob[(size_t)c * PQ + r]           = acc[mt][nt][0];
            ob[(size_t)(c + 1) * PQ + r]     = acc[mt][nt][1];
            ob[(size_t)c * PQ + r + 8]       = acc[mt][nt][2];
            ob[(size_t)(c + 1) * PQ + r + 8] = acc[mt][nt][3];
        }
    }
}

// ---------------------------------------------------------------------------
extern "C" void kernel_launch(void* const* d_in, const int* in_sizes, int n_in,
                              void* d_out, int out_size)
{
    const float* x     = (const float*)d_in[0];
    const float* Wq    = (const float*)d_in[1];
    const float* Wk    = (const float*)d_in[2];
    const float* Wv    = (const float*)d_in[3];
    const float* W1    = (const float*)d_in[4];
    const float* W2    = (const float*)d_in[5];
    const float* gamma = (const float*)d_in[6];
    const float* beta  = (const float*)d_in[7];
    const float* mean  = (const float*)d_in[8];
    const float* var   = (const float*)d_in[9];
    float* out = (float*)d_out;

    static cudaStream_t s2;
    static cudaEvent_t evFork, evJoin;
    static int init_done = 0;
    if (!init_done) {
        cudaFuncSetAttribute(k_gemm_qkv, cudaFuncAttributeMaxDynamicSharedMemorySize, F16_ARES_SMEM);
        cudaFuncSetAttribute(k_gemm_w1,  cudaFuncAttributeMaxDynamicSharedMemorySize, F16_ARES_SMEM);
        cudaStreamCreateWithFlags(&s2, cudaStreamNonBlocking);
        cudaEventCreateWithFlags(&evFork, cudaEventDisableTiming);
        cudaEventCreateWithFlags(&evJoin, cudaEventDisableTiming);
        init_done = 1;
    }

    // Round-8 structure: single fork for topk, everything else serial full-grid.
    cudaEventRecord(evFork, 0);
    cudaStreamWaitEvent(s2, evFork, 0);
    k_topk<<<dim3(TQ, BQ, 8), 256, 0, s2>>>(x);
    cudaEventRecord(evJoin, s2);

    k_roundw<<<256, 256>>>(Wq, Wk, Wv, W1, W2);
    k_transpose<<<dim3(PQ / 32, CQ / 32, BQ), dim3(32, 8)>>>(x, out);
    k_gemm_qkv<<<dim3(PQ / 128, BQ), 256, F16_ARES_SMEM>>>();

    cudaStreamWaitEvent(0, evJoin, 0);
    k_attn<<<dim3((BQ * PQ) / 64, 1, 1), 256>>>(gamma, beta, mean, var);
    k_gemm_w1<<<dim3(PQ / 128, BQ), 256, F16_ARES_SMEM>>>();
    k_gemm_w2<<<dim3(PQ / 128, 1, BQ), 256>>>(out);
}